// round 3
// baseline (speedup 1.0000x reference)
#include <cuda_runtime.h>
#include <cuda_bf16.h>
#include <math.h>

#define BB 128
#define PP 196
#define EE 256
#define AA 256
#define DD 512
#define MM 512
#define VV 10000
#define LL 26
#define TT 25
#define GG 2048
#define XKC 768
#define NPAD 10112          // 79 * 128
#define KP 1536             // 3 * 512 (bf16-split extended K)

// ---------------- device scratch ----------------
__device__ float g_mean[BB * EE];
__device__ float g_h[BB * DD];
__device__ float g_c[BB * DD];
__device__ float g_att1[BB * PP * AA];
__device__ float g_emb[TT * BB * MM];
__device__ float g_epre[TT * BB * GG];          // emb@Wih[:, :512].T + bih + bhh
__device__ float g_hall[TT * BB * DD];
__device__ float g_xhT[XKC * BB];               // [k][b]  k-major: [ctx(256)|h(512)]
__device__ float g_WcatT[DD * 512];             // [k][col]: col<256 Wd, else Wfb
__device__ float g_Wg[GG * XKC];                // [2048][768]: cols = [Wih_ctx | Whh]
__device__ float g_bias2[GG];                   // bih + bhh
__device__ __nv_bfloat16 g_Apack[TT * BB * KP]; // [3200][1536]
__device__ __nv_bfloat16 g_Wpack[NPAD * KP];    // [10112][1536]

// ---------------- setup kernels ----------------
__global__ void mean_kernel(const float* __restrict__ enc) {
    int b = blockIdx.x, e = threadIdx.x;
    const float* base = enc + (size_t)b * PP * EE + e;
    float s = 0.f;
    #pragma unroll 4
    for (int p = 0; p < PP; p++) s += base[(size_t)p * EE];
    g_mean[b * EE + e] = s * (1.0f / PP);
}

__global__ void prep_weights(const float* __restrict__ Wd, const float* __restrict__ Wfb,
                             const float* __restrict__ Wih, const float* __restrict__ Whh,
                             const float* __restrict__ bih, const float* __restrict__ bhh) {
    int i = blockIdx.x * blockDim.x + threadIdx.x;
    int stride = gridDim.x * blockDim.x;
    for (int idx = i; idx < DD * 512; idx += stride) {
        int k = idx >> 9, col = idx & 511;
        g_WcatT[idx] = (col < 256) ? Wd[col * DD + k] : Wfb[(col - 256) * DD + k];
    }
    for (int idx = i; idx < GG * XKC; idx += stride) {
        int j = idx / XKC, c = idx % XKC;
        g_Wg[idx] = (c < 256) ? Wih[j * XKC + 512 + c] : Whh[j * DD + (c - 256)];
    }
    for (int idx = i; idx < GG; idx += stride) g_bias2[idx] = bih[idx] + bhh[idx];
}

__global__ void gather_emb(const int* __restrict__ captions, const float* __restrict__ embW) {
    int r = blockIdx.x;
    int t = r >> 7, b = r & 127;
    int tok = captions[b * LL + t];
    const float4* src = (const float4*)(embW + (size_t)tok * MM);
    float4* dst = (float4*)(g_emb + (size_t)r * MM);
    dst[threadIdx.x] = src[threadIdx.x];
}

// split fp32 into hi/lo bf16: W' = [Whi | Whi | Wlo]
__global__ void pack_W(const float* __restrict__ Wfc) {
    int n = blockIdx.x;
    for (int k = threadIdx.x; k < 512; k += blockDim.x) {
        __nv_bfloat16 hi, lo;
        if (n < VV) {
            float x = Wfc[(size_t)n * 512 + k];
            hi = __float2bfloat16(x);
            lo = __float2bfloat16(x - __bfloat162float(hi));
        } else { hi = __float2bfloat16(0.f); lo = hi; }
        g_Wpack[(size_t)n * KP + k] = hi;
        g_Wpack[(size_t)n * KP + 512 + k] = hi;
        g_Wpack[(size_t)n * KP + 1024 + k] = lo;
    }
}

// A' = [Ahi | Alo | Ahi]
__global__ void pack_A() {
    int r = blockIdx.x;
    for (int k = threadIdx.x; k < 512; k += blockDim.x) {
        float x = g_hall[(size_t)r * 512 + k];
        __nv_bfloat16 hi = __float2bfloat16(x);
        __nv_bfloat16 lo = __float2bfloat16(x - __bfloat162float(hi));
        g_Apack[(size_t)r * KP + k] = hi;
        g_Apack[(size_t)r * KP + 512 + k] = lo;
        g_Apack[(size_t)r * KP + 1024 + k] = hi;
    }
}

// ---------------- generic 128x128 SGEMM (setup: att1, epre) ----------------
__global__ __launch_bounds__(256) void sgemm128(
    int N, int K,
    const float* __restrict__ Amat, int lda,
    const float* __restrict__ Wmat, int ldw,
    const float* __restrict__ bias,
    float* __restrict__ Cout) {
    const int bx = blockIdx.x, by = blockIdx.y;
    __shared__ float As[8][128];
    __shared__ float Ws[8][128];
    const int tid = threadIdx.x;
    const int lRow = tid >> 1;
    const int lCol = (tid & 1) << 2;
    const float* Aptr = Amat + (size_t)(by * 128 + lRow) * lda + lCol;
    const float* Wptr = Wmat + (size_t)(bx * 128 + lRow) * ldw + lCol;
    const int trow = tid >> 4, tcol = tid & 15;
    float acc[8][8] = {};
    for (int k0 = 0; k0 < K; k0 += 8) {
        float4 av = *(const float4*)(Aptr + k0);
        float4 wv = *(const float4*)(Wptr + k0);
        As[lCol + 0][lRow] = av.x; As[lCol + 1][lRow] = av.y;
        As[lCol + 2][lRow] = av.z; As[lCol + 3][lRow] = av.w;
        Ws[lCol + 0][lRow] = wv.x; Ws[lCol + 1][lRow] = wv.y;
        Ws[lCol + 2][lRow] = wv.z; Ws[lCol + 3][lRow] = wv.w;
        __syncthreads();
        #pragma unroll
        for (int k = 0; k < 8; k++) {
            float a[8], w[8];
            *(float4*)(a)     = *(const float4*)&As[k][trow * 8];
            *(float4*)(a + 4) = *(const float4*)&As[k][trow * 8 + 4];
            *(float4*)(w)     = *(const float4*)&Ws[k][tcol * 8];
            *(float4*)(w + 4) = *(const float4*)&Ws[k][tcol * 8 + 4];
            #pragma unroll
            for (int i = 0; i < 8; i++)
                #pragma unroll
                for (int j = 0; j < 8; j++)
                    acc[i][j] += a[i] * w[j];
        }
        __syncthreads();
    }
    #pragma unroll
    for (int i = 0; i < 8; i++) {
        int m = by * 128 + trow * 8 + i;
        #pragma unroll
        for (int j4 = 0; j4 < 8; j4 += 4) {
            int n = bx * 128 + tcol * 8 + j4;
            float4 v = make_float4(acc[i][j4], acc[i][j4 + 1], acc[i][j4 + 2], acc[i][j4 + 3]);
            if (bias) { v.x += bias[n]; v.y += bias[n + 1]; v.z += bias[n + 2]; v.w += bias[n + 3]; }
            *(float4*)(Cout + (size_t)m * N + n) = v;
        }
    }
}

// ---------------- skinny SGEMM (h0/c0 init) ----------------
__global__ __launch_bounds__(128) void sgemm_skinny(
    int N, int kLen,
    const float* __restrict__ Amat, int lda,
    const float* __restrict__ Wmat, int ldw,
    const float* __restrict__ bias,
    float* __restrict__ Cout) {
    const int bx = blockIdx.x;
    __shared__ float As[32][132];
    __shared__ float Ws[32][36];
    const int tid = threadIdx.x;
    const int trow = tid >> 3;
    const int tcol = tid & 7;
    float acc[8][4] = {};
    for (int k0 = 0; k0 < kLen; k0 += 32) {
        #pragma unroll
        for (int i = 0; i < 8; i++) {
            int idx = tid + i * 128;
            int r = idx >> 3;
            int c4 = (idx & 7) << 2;
            float4 v = *(const float4*)(Amat + (size_t)r * lda + k0 + c4);
            As[c4 + 0][r] = v.x; As[c4 + 1][r] = v.y; As[c4 + 2][r] = v.z; As[c4 + 3][r] = v.w;
        }
        #pragma unroll
        for (int i = 0; i < 2; i++) {
            int idx = tid + i * 128;
            int r = idx >> 3;
            int c4 = (idx & 7) << 2;
            float4 v = *(const float4*)(Wmat + (size_t)(bx * 32 + r) * ldw + k0 + c4);
            Ws[c4 + 0][r] = v.x; Ws[c4 + 1][r] = v.y; Ws[c4 + 2][r] = v.z; Ws[c4 + 3][r] = v.w;
        }
        __syncthreads();
        #pragma unroll
        for (int k = 0; k < 32; k++) {
            float a[8];
            *(float4*)(a)     = *(const float4*)&As[k][trow * 8];
            *(float4*)(a + 4) = *(const float4*)&As[k][trow * 8 + 4];
            float4 w = *(const float4*)&Ws[k][tcol * 4];
            #pragma unroll
            for (int i = 0; i < 8; i++) {
                acc[i][0] += a[i] * w.x;
                acc[i][1] += a[i] * w.y;
                acc[i][2] += a[i] * w.z;
                acc[i][3] += a[i] * w.w;
            }
        }
        __syncthreads();
    }
    #pragma unroll
    for (int i = 0; i < 8; i++) {
        int m = trow * 8 + i;
        int n = bx * 32 + tcol * 4;
        float4 v = make_float4(acc[i][0], acc[i][1], acc[i][2], acc[i][3]);
        if (bias) { v.x += bias[n]; v.y += bias[n + 1]; v.z += bias[n + 2]; v.w += bias[n + 3]; }
        *(float4*)(Cout + (size_t)m * N + n) = v;
    }
}

// ---------------- per-step fused: hproj + attention + gate + xhT ----------------
__global__ __launch_bounds__(512) void attn_full(
    int t,
    const float* __restrict__ enc, const int* __restrict__ lengths,
    const float* __restrict__ bd, const float* __restrict__ bfb,
    const float* __restrict__ wf, const float* __restrict__ bfp,
    float* __restrict__ alpha_out) {
    const int b = blockIdx.x, tid = threadIdx.x;
    __shared__ float hs[512];
    __shared__ float wfs[256];
    __shared__ float att2s[256];
    __shared__ float gs[256];
    __shared__ float sc[200];
    __shared__ float red[512];
    __shared__ float part[4 * 512];   // hproj split-K partials
    __shared__ float ctxp[8 * 256];   // ctx split-P partials

    hs[tid] = g_h[b * DD + tid];
    if (tid < 256) wfs[tid] = wf[tid];
    __syncthreads();

    // hproj: 512 cols of [att2|gatepre] = h @ [Wd;Wfb]^T, split-K by 4
    {
        const int cg = tid & 127;        // col group: cols 4cg..4cg+3
        const int kq = tid >> 7;         // k quarter
        float4 acc4 = make_float4(0.f, 0.f, 0.f, 0.f);
        const float* wp = g_WcatT + (size_t)(kq * 128) * 512 + cg * 4;
        const float* hp = hs + kq * 128;
        #pragma unroll 4
        for (int ki = 0; ki < 128; ki++) {
            float4 w4 = *(const float4*)(wp + (size_t)ki * 512);
            float xv = hp[ki];
            acc4.x += xv * w4.x; acc4.y += xv * w4.y;
            acc4.z += xv * w4.z; acc4.w += xv * w4.w;
        }
        *(float4*)&part[kq * 512 + cg * 4] = acc4;
    }
    __syncthreads();
    {
        float s = part[tid] + part[512 + tid] + part[1024 + tid] + part[1536 + tid];
        if (tid < 256) att2s[tid] = s + bd[tid];
        else gs[tid - 256] = s + bfb[tid - 256];
    }
    __syncthreads();

    // scores over P=196
    float score = -3.0e38f;
    float e = 0.f;
    if (tid < PP) {
        const float4* arow = (const float4*)(g_att1 + ((size_t)b * PP + tid) * AA);
        float s0 = 0, s1 = 0, s2 = 0, s3 = 0;
        #pragma unroll 8
        for (int a4 = 0; a4 < AA / 4; a4++) {
            float4 av = arow[a4];
            int a = a4 * 4;
            s0 += fmaxf(av.x + att2s[a + 0], 0.f) * wfs[a + 0];
            s1 += fmaxf(av.y + att2s[a + 1], 0.f) * wfs[a + 1];
            s2 += fmaxf(av.z + att2s[a + 2], 0.f) * wfs[a + 2];
            s3 += fmaxf(av.w + att2s[a + 3], 0.f) * wfs[a + 3];
        }
        score = s0 + s1 + s2 + s3 + bfp[0];
    }
    red[tid] = score;
    __syncthreads();
    for (int off = 256; off > 0; off >>= 1) {
        if (tid < off) red[tid] = fmaxf(red[tid], red[tid + off]);
        __syncthreads();
    }
    float mx = red[0];
    __syncthreads();
    if (tid < PP) e = expf(score - mx);
    red[tid] = (tid < PP) ? e : 0.f;
    __syncthreads();
    for (int off = 256; off > 0; off >>= 1) {
        if (tid < off) red[tid] += red[tid + off];
        __syncthreads();
    }
    float inv = 1.f / red[0];
    __syncthreads();
    const int active = t < (lengths[b] - 1);
    if (tid < PP) {
        float al = e * inv;
        sc[tid] = al;
        alpha_out[((size_t)b * TT + t) * PP + tid] = active ? al : 0.f;
    }
    __syncthreads();

    // ctx: split P into 8 chunks; thread = (half, e4): 4 e's each
    {
        const int e4 = tid & 63;          // e = 4*e4..+3
        const int half = tid >> 6;        // 0..7
        int p0 = half * 25;
        int p1 = min(PP, p0 + 25);
        float4 cacc = make_float4(0.f, 0.f, 0.f, 0.f);
        const float4* eb = (const float4*)(enc + (size_t)b * PP * EE) + e4;
        for (int p = p0; p < p1; p++) {
            float4 ev = eb[(size_t)p * (EE / 4)];
            float al = sc[p];
            cacc.x += al * ev.x; cacc.y += al * ev.y;
            cacc.z += al * ev.z; cacc.w += al * ev.w;
        }
        *(float4*)&ctxp[half * 256 + e4 * 4] = cacc;
    }
    __syncthreads();
    if (tid < 256) {
        float ctx = 0.f;
        #pragma unroll
        for (int h = 0; h < 8; h++) ctx += ctxp[h * 256 + tid];
        float gate = 1.f / (1.f + expf(-gs[tid]));
        g_xhT[tid * BB + b] = ctx * gate;
    }
    g_xhT[(256 + tid) * BB + b] = hs[tid];
}

// ---------------- per-step fused: gates GEMM + LSTM pointwise ----------------
__global__ __launch_bounds__(512) void gates_lstm(int t, const int* __restrict__ lengths) {
    const int j = blockIdx.x;            // d-range [4j, 4j+4)
    const int tid = threadIdx.x;
    const int b = tid & 127, q = tid >> 7;
    __shared__ float xs[64 * 128];       // 32KB chunk of xhT
    __shared__ float gsh[4 * 512];       // [q][b*4+dl]
    const int mylen = lengths[tid & 127];
    float acc[4] = {0.f, 0.f, 0.f, 0.f};
    const float* w0 = g_Wg + (size_t)(q * 512 + 4 * j) * XKC;

    for (int k0 = 0; k0 < XKC; k0 += 64) {
        // cooperative load of xhT[k0..k0+64)[all b] : 8192 floats
        const float4* src = (const float4*)(g_xhT + (size_t)k0 * BB);
        float4* dst = (float4*)xs;
        #pragma unroll
        for (int u = 0; u < 4; u++) dst[tid + u * 512] = src[tid + u * 512];
        __syncthreads();
        #pragma unroll 4
        for (int kl = 0; kl < 64; kl += 4) {
            float x0 = xs[(kl + 0) * 128 + b];
            float x1 = xs[(kl + 1) * 128 + b];
            float x2 = xs[(kl + 2) * 128 + b];
            float x3 = xs[(kl + 3) * 128 + b];
            #pragma unroll
            for (int dl = 0; dl < 4; dl++) {
                float4 w4 = *(const float4*)(w0 + (size_t)dl * XKC + k0 + kl);
                acc[dl] += x0 * w4.x + x1 * w4.y + x2 * w4.z + x3 * w4.w;
            }
        }
        __syncthreads();
    }
    #pragma unroll
    for (int dl = 0; dl < 4; dl++) gsh[q * 512 + b * 4 + dl] = acc[dl];
    __syncthreads();

    // pointwise: thread = (b2, dl)
    {
        const int b2 = tid & 127, dl = tid >> 7;
        const int d = 4 * j + dl;
        const size_t row = (size_t)t * BB + b2;
        float gi = gsh[0 * 512 + b2 * 4 + dl] + g_epre[row * GG + d];
        float gf = gsh[1 * 512 + b2 * 4 + dl] + g_epre[row * GG + 512 + d];
        float gg = gsh[2 * 512 + b2 * 4 + dl] + g_epre[row * GG + 1024 + d];
        float go = gsh[3 * 512 + b2 * 4 + dl] + g_epre[row * GG + 1536 + d];
        float ig = 1.f / (1.f + expf(-gi));
        float fg = 1.f / (1.f + expf(-gf));
        float g2 = tanhf(gg);
        float og = 1.f / (1.f + expf(-go));
        float c = g_c[b2 * DD + d];
        float cn = fg * c + ig * g2;
        float hn = og * tanhf(cn);
        g_hall[row * DD + d] = hn;
        if (t < mylen - 1) {
            g_h[b2 * DD + d] = hn;
            g_c[b2 * DD + d] = cn;
        }
    }
}

// ---------------- bf16 tensor-core vocab GEMM ----------------
__device__ __forceinline__ void mma16816(float* c, const unsigned* a, const unsigned* bb) {
    asm volatile(
        "mma.sync.aligned.m16n8k16.row.col.f32.bf16.bf16.f32 "
        "{%0,%1,%2,%3}, {%4,%5,%6,%7}, {%8,%9}, {%0,%1,%2,%3};\n"
        : "+f"(c[0]), "+f"(c[1]), "+f"(c[2]), "+f"(c[3])
        : "r"(a[0]), "r"(a[1]), "r"(a[2]), "r"(a[3]), "r"(bb[0]), "r"(bb[1]));
}

__global__ __launch_bounds__(256) void gemm_bf16(
    const int* __restrict__ lengths, const float* __restrict__ bfc,
    float* __restrict__ out) {
    const int bn = blockIdx.x, t = blockIdx.y;
    __shared__ __align__(16) unsigned As[2][128 * 12];
    __shared__ __align__(16) unsigned Bs[2][128 * 12];
    __shared__ int lensh[128];
    const int tid = threadIdx.x;
    const int w = tid >> 5, l = tid & 31;
    const int wm = w & 1, wn = w >> 1;
    const int g = l >> 2, tg = l & 3;
    if (tid < 128) lensh[tid] = lengths[tid];

    const int lrow = tid >> 1, lhalf = tid & 1;
    const __nv_bfloat16* aSrc = g_Apack + (size_t)(t * 128 + lrow) * KP + lhalf * 8;
    const __nv_bfloat16* bSrc = g_Wpack + (size_t)(bn * 128 + lrow) * KP + lhalf * 8;
    const int sIdx = lrow * 12 + lhalf * 4;

    float c[4][4][4] = {};
    uint4 av = *(const uint4*)aSrc;
    uint4 bv = *(const uint4*)bSrc;
    *(uint4*)&As[0][sIdx] = av;
    *(uint4*)&Bs[0][sIdx] = bv;
    __syncthreads();

    const int NK = KP / 16;   // 96
    for (int k0 = 0; k0 < NK; k0++) {
        int cur = k0 & 1;
        if (k0 + 1 < NK) {
            av = *(const uint4*)(aSrc + (size_t)(k0 + 1) * 16);
            bv = *(const uint4*)(bSrc + (size_t)(k0 + 1) * 16);
        }
        const unsigned* Ac = As[cur];
        const unsigned* Bc = Bs[cur];
        unsigned af[4][4], bf[4][2];
        #pragma unroll
        for (int mi = 0; mi < 4; mi++) {
            int r = wm * 64 + mi * 16 + g;
            af[mi][0] = Ac[r * 12 + tg];
            af[mi][1] = Ac[(r + 8) * 12 + tg];
            af[mi][2] = Ac[r * 12 + tg + 4];
            af[mi][3] = Ac[(r + 8) * 12 + tg + 4];
        }
        #pragma unroll
        for (int ni = 0; ni < 4; ni++) {
            int cc = wn * 32 + ni * 8 + g;
            bf[ni][0] = Bc[cc * 12 + tg];
            bf[ni][1] = Bc[cc * 12 + tg + 4];
        }
        #pragma unroll
        for (int mi = 0; mi < 4; mi++)
            #pragma unroll
            for (int ni = 0; ni < 4; ni++)
                mma16816(c[mi][ni], af[mi], bf[ni]);
        if (k0 + 1 < NK) {
            int nxt = cur ^ 1;
            *(uint4*)&As[nxt][sIdx] = av;
            *(uint4*)&Bs[nxt][sIdx] = bv;
            __syncthreads();
        }
    }

    // epilogue
    #pragma unroll
    for (int mi = 0; mi < 4; mi++) {
        #pragma unroll
        for (int half = 0; half < 2; half++) {
            int row = wm * 64 + mi * 16 + g + half * 8;
            int b = row;
            bool act = t < (lensh[b] - 1);
            float* orow = out + (size_t)b * TT * VV + (size_t)t * VV;
            #pragma unroll
            for (int ni = 0; ni < 4; ni++) {
                int n = bn * 128 + wn * 32 + ni * 8 + tg * 2;
                if (n < VV) {
                    float v0 = act ? c[mi][ni][half * 2 + 0] + bfc[n] : 0.f;
                    orow[n] = v0;
                }
                if (n + 1 < VV) {
                    float v1 = act ? c[mi][ni][half * 2 + 1] + bfc[n + 1] : 0.f;
                    orow[n + 1] = v1;
                }
            }
        }
    }
}

// ---------------- launch ----------------
extern "C" void kernel_launch(void* const* d_in, const int* in_sizes, int n_in,
                              void* d_out, int out_size) {
    const float* enc      = (const float*)d_in[0];
    const int*   captions = (const int*)d_in[1];
    const int*   lengths  = (const int*)d_in[2];
    const float* embW     = (const float*)d_in[3];
    const float* We       = (const float*)d_in[4];
    const float* be       = (const float*)d_in[5];
    const float* Wd       = (const float*)d_in[6];
    const float* bd       = (const float*)d_in[7];
    const float* wf       = (const float*)d_in[8];
    const float* bfp      = (const float*)d_in[9];
    const float* Wih      = (const float*)d_in[10];
    const float* bih      = (const float*)d_in[11];
    const float* Whh      = (const float*)d_in[12];
    const float* bhh      = (const float*)d_in[13];
    const float* Wh0      = (const float*)d_in[14];
    const float* bh0      = (const float*)d_in[15];
    const float* Wc0      = (const float*)d_in[16];
    const float* bc0      = (const float*)d_in[17];
    const float* Wfb      = (const float*)d_in[18];
    const float* bfb      = (const float*)d_in[19];
    const float* Wfc      = (const float*)d_in[20];
    const float* bfc      = (const float*)d_in[21];
    float* out = (float*)d_out;
    float* alpha_out = out + (size_t)BB * TT * VV;

    float *p_mean, *p_h, *p_c, *p_att1, *p_emb, *p_epre, *p_bias2;
    cudaGetSymbolAddress((void**)&p_mean,  g_mean);
    cudaGetSymbolAddress((void**)&p_h,     g_h);
    cudaGetSymbolAddress((void**)&p_c,     g_c);
    cudaGetSymbolAddress((void**)&p_att1,  g_att1);
    cudaGetSymbolAddress((void**)&p_emb,   g_emb);
    cudaGetSymbolAddress((void**)&p_epre,  g_epre);
    cudaGetSymbolAddress((void**)&p_bias2, g_bias2);

    // ---- setup (loop-invariant) ----
    mean_kernel<<<BB, EE>>>(enc);
    prep_weights<<<1024, 256>>>(Wd, Wfb, Wih, Whh, bih, bhh);
    gather_emb<<<TT * BB, 128>>>(captions, embW);
    pack_W<<<NPAD, 256>>>(Wfc);
    sgemm_skinny<<<16, 128>>>(512, 256, p_mean, EE, Wh0, EE, bh0, p_h);
    sgemm_skinny<<<16, 128>>>(512, 256, p_mean, EE, Wc0, EE, bc0, p_c);
    sgemm128<<<dim3(AA / 128, BB * PP / 128), 256>>>(AA, EE, enc, EE, We, EE, be, p_att1);
    sgemm128<<<dim3(GG / 128, TT * BB / 128), 256>>>(GG, MM, p_emb, MM, Wih, XKC, p_bias2, p_epre);

    // ---- recurrence: 2 kernels per step ----
    for (int t = 0; t < TT; t++) {
        attn_full<<<BB, 512>>>(t, enc, lengths, bd, bfb, wf, bfp, alpha_out);
        gates_lstm<<<BB, 512>>>(t, lengths);
    }

    // ---- vocab head: bf16-split tensor cores ----
    pack_A<<<TT * BB, 256>>>();
    gemm_bf16<<<dim3(NPAD / 128, TT), 256>>>(lengths, bfc, out);
}